// round 3
// baseline (speedup 1.0000x reference)
#include <cuda_runtime.h>
#include <math.h>

// ---------------- problem constants ----------------
#define HOPSZ 551
#define MAXH  2048      // H = N/551 + 1 = 1903 for N = 1<<20
#define LCH   16        // samples per chunk (one chunk per thread)
#define WARM  96        // warmup: pole radius <=0.72 -> transient ~2e-9
#define TPB   448       // 14 warps/block; 65536/448 -> 147 blocks ~ 1/SM

// scratch (device globals; no allocation allowed)
__device__ float g_cb[MAXH * 5];
__device__ float g_cd[MAXH * 5];
__device__ float g_p[MAXH];

// ---------------- kernel 1: per-hop coefficients ----------------
__global__ void coef_kernel(
    const float* __restrict__ g2,
    const float* __restrict__ depth, const float* __restrict__ bias,
    const float* __restrict__ lfo_omega, const float* __restrict__ lfo_phi,
    const float* __restrict__ lfo_r_logit,
    const float* __restrict__ W_in, const float* __restrict__ b_in,
    const float* __restrict__ W_h, const float* __restrict__ b_h,
    const float* __restrict__ W_out, const float* __restrict__ b_out,
    float* __restrict__ out, int N, int H, int out_size)
{
    int t = blockIdx.x * blockDim.x + threadIdx.x;
    if (t >= H) return;

    float r  = 1.0f / (1.0f + expf(-lfo_r_logit[0]));
    float tf = (float)t;
    float amp = expf(tf * logf(r));          // r^t
    float ph  = lfo_omega[0] * tf + lfo_phi[0];
    float l0 = amp * cosf(ph);
    float l1 = amp * sinf(ph);

    float h[16];
#pragma unroll
    for (int j = 0; j < 16; j++)
        h[j] = tanhf(l0 * W_in[j] + l1 * W_in[16 + j] + b_in[j]);

    for (int lay = 0; lay < 2; lay++) {
        float hn[16];
#pragma unroll
        for (int j = 0; j < 16; j++) {
            float s = b_h[lay * 16 + j];
#pragma unroll
            for (int i = 0; i < 16; i++)
                s += h[i] * W_h[lay * 256 + i * 16 + j];
            hn[j] = tanhf(s);
        }
#pragma unroll
        for (int j = 0; j < 16; j++) h[j] = hn[j];
    }
    float s = b_out[0];
#pragma unroll
    for (int i = 0; i < 16; i++) s += h[i] * W_out[i];
    float ws = tanhf(s);

    float d  = bias[0] + depth[0] * 0.5f * (1.0f + ws);
    float td = tanf(d);
    float p  = tanhf((1.0f - td) / (1.0f + td));

    float p2 = p * p, p3 = p2 * p, p4 = p2 * p2;
    float bap[5] = { p4, -4.0f * p3, 6.0f * p2, -4.0f * p, 1.0f };
    float aap[5] = { 1.0f, -4.0f * p, 6.0f * p2, -4.0f * p3, p4 };
    float ag2 = fabsf(g2[0]);
    float den[5];
#pragma unroll
    for (int k = 0; k < 5; k++) den[k] = aap[k] - ag2 * bap[k];
    float d0 = den[0];
#pragma unroll
    for (int k = 0; k < 5; k++) {
        g_cb[t * 5 + k] = bap[k] / d0;
        g_cd[t * 5 + k] = den[k] / d0;
    }
    g_p[t] = p;
    if (N + t < out_size) out[N + t] = p;   // second output: p (H,)
}

// Fills any output tail beyond N+H (defensive; normally empty).
__global__ void tail_kernel(float* __restrict__ out, int N, int H, int out_size)
{
    float pv = g_p[H - 1];
    for (int idx = N + H + blockIdx.x * blockDim.x + threadIdx.x;
         idx < out_size; idx += gridDim.x * blockDim.x)
        out[idx] = pv;
}

// ---------------- kernel 2: fused biquad + TV-FIR + TV-LPC ----------------
// One thread per LCH-sample chunk; re-runs recurrences from start-WARM with
// zero state. Lanes are LCH=16 floats apart -> pad shared every 16 words
// (addr stride becomes 17 -> conflict-free).
static __device__ __forceinline__ int padj(int j) { return j + (j >> 4); }

__global__ void __launch_bounds__(TPB)
phaser_kernel(
    const float* __restrict__ x, const float* __restrict__ g1,
    const float* __restrict__ bq_dc, const float* __restrict__ bq_ff,
    const float* __restrict__ bq_fb,
    float* __restrict__ out, int N, int H, int outLim)
{
    constexpr int REG = TPB * LCH + WARM + 2;
    __shared__ float xs[REG + (REG >> 4) + 4];

    const int blockFirst  = blockIdx.x * TPB;          // first chunk id
    const int regionStart = blockFirst * LCH - WARM - 2;

    // coalesced staging of x (zeros outside [0,N))
    for (int j = threadIdx.x; j < REG; j += TPB) {
        int g = regionStart + j;
        xs[padj(j)] = (g >= 0 && g < N) ? x[g] : 0.0f;
    }
    __syncthreads();

    const int c     = blockFirst + threadIdx.x;
    const int start = c * LCH;
    if (start >= N) return;
    int nstart = start - WARM; if (nstart < 0) nstart = 0;
    int nend   = start + LCH;  if (nend > N)   nend = N;

    // biquad coefficients (stability-triangle parameterization)
    const float b0  = bq_dc[0], b1c = bq_ff[0], b2c = bq_ff[1];
    const float a1  = 2.0f * tanhf(bq_fb[0]);
    const float aa1 = fabsf(a1);
    const float a2  = ((2.0f - aa1) * tanhf(bq_fb[1]) + aa1) * 0.5f;
    const float g1v = g1[0];
    const float scaleF   = (float)((double)(H - 1) / (double)(N - 1));
    const float invScale = (float)((double)(N - 1) / (double)(H - 1));

    // x history (from shared; region includes 2 lead-in samples)
    int jb = nstart - regionStart;
    float x1 = xs[padj(jb - 1)];
    float x2 = xs[padj(jb - 2)];
    // filter state (zero at nstart)
    float f1 = 0.f, f2 = 0.f, f3 = 0.f, f4 = 0.f;
    float y1 = 0.f, y2v = 0.f, y3 = 0.f, y4 = 0.f;

    // exact (reference-formula) hop index for a sample
    auto i0_of = [&](int m) {
        float pos = (float)m * scaleF;
        int i = (int)floorf(pos);
        return i < 0 ? 0 : (i > H - 2 ? H - 2 : i);
    };

    int n = nstart;
    int j = nstart - regionStart;
    while (n < nend) {
        int i0 = i0_of(n);
        int ncross;
        if (i0 >= H - 2) {
            ncross = nend;                   // clamped region runs to the end
        } else {
            ncross = (int)((float)(i0 + 1) * invScale);   // approx boundary
            while (ncross > n && i0_of(ncross) > i0) ncross--;
            while (ncross < nend && i0_of(ncross) == i0) ncross++;
            if (ncross > nend) ncross = nend;
        }

        // segment-constant coefficient rows
        const float* rb = g_cb + i0 * 5;
        const float* rd = g_cd + i0 * 5;
        float cb00 = rb[0], cb01 = rb[1], cb02 = rb[2], cb03 = rb[3], cb04 = rb[4];
        float cbd0 = rb[5] - cb00, cbd1 = rb[6] - cb01, cbd2 = rb[7] - cb02,
              cbd3 = rb[8] - cb03, cbd4 = rb[9] - cb04;
        float cd01 = rd[1], cd02 = rd[2], cd03 = rd[3], cd04 = rd[4];
        float cdd1 = rd[6] - cd01, cdd2 = rd[7] - cd02,
              cdd3 = rd[8] - cd03, cdd4 = rd[9] - cd04;

        float pos0 = (float)n * scaleF;      // exact at segment start
        float frac = pos0 - (float)i0;

#pragma unroll 4
        for (; n < ncross; ++n, ++j) {
            float xv = xs[padj(j)];
            // pre-filter biquad
            float v1   = fmaf(b2c, x2, fmaf(b1c, x1, b0 * xv));
            x2 = x1; x1 = xv;
            float hcur = fmaf(-a2, f2, fmaf(-a1, f1, v1));
            // interp coeffs (segment-constant base + slope)
            float c0 = fmaf(frac, cbd0, cb00);
            float c1 = fmaf(frac, cbd1, cb01);
            float c2 = fmaf(frac, cbd2, cb02);
            float c3 = fmaf(frac, cbd3, cb03);
            float c4 = fmaf(frac, cbd4, cb04);
            float v = fmaf(c1, f1, fmaf(c2, f2, fmaf(c3, f3, c4 * f4)));
            v = fmaf(c0, hcur, v);
            float d1 = fmaf(frac, cdd1, cd01);
            float d2 = fmaf(frac, cdd2, cd02);
            float d3 = fmaf(frac, cdd3, cd03);
            float d4 = fmaf(frac, cdd4, cd04);
            float tmp = v - fmaf(d2, y2v, fmaf(d3, y3, d4 * y4));
            float yv  = fmaf(-d1, y1, tmp);
            y4 = y3; y3 = y2v; y2v = y1; y1 = yv;
            f4 = f3; f3 = f2;  f2 = f1;  f1 = hcur;
            frac += scaleF;
            if (n >= start && n < outLim)
                out[n] = fmaf(g1v, hcur, yv);
        }
    }
}

// ---------------- launch ----------------
extern "C" void kernel_launch(void* const* d_in, const int* in_sizes, int n_in,
                              void* d_out, int out_size)
{
    const float* x      = (const float*)d_in[0];
    const float* g1     = (const float*)d_in[1];
    const float* g2     = (const float*)d_in[2];
    const float* depth  = (const float*)d_in[3];
    const float* bias   = (const float*)d_in[4];
    const float* lfo_o  = (const float*)d_in[5];
    const float* lfo_p  = (const float*)d_in[6];
    const float* lfo_r  = (const float*)d_in[7];
    const float* W_in   = (const float*)d_in[8];
    const float* b_in   = (const float*)d_in[9];
    const float* W_h    = (const float*)d_in[10];
    const float* b_h    = (const float*)d_in[11];
    const float* W_out  = (const float*)d_in[12];
    const float* b_out  = (const float*)d_in[13];
    const float* bq_dc  = (const float*)d_in[14];
    const float* bq_ff  = (const float*)d_in[15];
    const float* bq_fb  = (const float*)d_in[16];
    float* out = (float*)d_out;

    int N = in_sizes[0];
    int H = N / HOPSZ + 1;

    int cblocks = (H + 127) / 128;
    coef_kernel<<<cblocks, 128>>>(g2, depth, bias, lfo_o, lfo_p, lfo_r,
                                  W_in, b_in, W_h, b_h, W_out, b_out,
                                  out, N, H, out_size);

    if (out_size > N + H)
        tail_kernel<<<4, 128>>>(out, N, H, out_size);

    int C = (N + LCH - 1) / LCH;
    int blocks = (C + TPB - 1) / TPB;
    int outLim = out_size < N ? out_size : N;
    phaser_kernel<<<blocks, TPB>>>(x, g1, bq_dc, bq_ff, bq_fb,
                                   out, N, H, outLim);
}

// round 4
// speedup vs baseline: 1.4628x; 1.4628x over previous
#include <cuda_runtime.h>
#include <math.h>

// ---------------- tuning ----------------
#define LCH  32     // samples per chunk (one chunk per thread)
#define WARM 96     // warmup samples (worst perturbed pole ~0.84 -> 5e-8)
#define TPB  128    // threads per block -> block covers TPB*LCH samples
#define NCH  12     // max hop-coefficient rows a block can need (<=10 actual)

// Single fused kernel: per-block hop-coefficient MLP (into shared) +
// chunked biquad + TV-FIR + TV-LPC with zero-state warmup.
__global__ void __launch_bounds__(TPB)
phaser_all(const float* __restrict__ x,
           const float* __restrict__ g1, const float* __restrict__ g2,
           const float* __restrict__ depth, const float* __restrict__ bias,
           const float* __restrict__ lfo_omega, const float* __restrict__ lfo_phi,
           const float* __restrict__ lfo_r_logit,
           const float* __restrict__ W_in, const float* __restrict__ b_in,
           const float* __restrict__ W_h, const float* __restrict__ b_h,
           const float* __restrict__ W_out, const float* __restrict__ b_out,
           const float* __restrict__ bq_dc, const float* __restrict__ bq_ff,
           const float* __restrict__ bq_fb,
           float* __restrict__ out, int N, int H, int out_size)
{
    constexpr int REGN = TPB * LCH + WARM + 2;
    __shared__ float xs[REGN + (REGN >> 5) + 8];   // pad every 32 -> stride 33
    __shared__ float sc[NCH * 10];                 // per hop: cb[0..4], cd[0..4]

    const int blockFirst  = blockIdx.x * TPB;
    const int regionStart = blockFirst * LCH - WARM - 2;
    const float scaleF = (float)((double)(H - 1) / (double)(N - 1));
    const int Hm2 = (H - 2) > 0 ? (H - 2) : 0;

    // ---- stage x into shared (coalesced; zeros outside [0,N)) ----
    for (int j = threadIdx.x; j < REGN; j += TPB) {
        int g = regionStart + j;
        xs[j + (j >> 5)] = (g >= 0 && g < N) ? x[g] : 0.f;
    }

    // ---- per-block hop coefficient rows (threads 0..nh-1) ----
    int nmin = regionStart + 2; if (nmin < 0) nmin = 0;
    int nmax = blockFirst * LCH + TPB * LCH; if (nmax > N) nmax = N;   // exclusive
    int i0min = (int)floorf((float)nmin * scaleF);
    if (i0min < 0) i0min = 0; if (i0min > Hm2) i0min = Hm2;
    int i0max = (int)floorf((float)(nmax - 1) * scaleF);
    if (i0max < 0) i0max = 0; if (i0max > Hm2) i0max = Hm2;
    const int h0 = i0min;
    int nh = i0max + 2 - h0; if (nh > NCH) nh = NCH;

    if (threadIdx.x < nh) {
        int t = h0 + threadIdx.x;                 // hop index, <= H-1
        // damped-oscillator LFO
        float r   = 1.f / (1.f + expf(-lfo_r_logit[0]));
        float tf  = (float)t;
        float amp = expf(tf * logf(r));           // r^t
        float ph  = lfo_omega[0] * tf + lfo_phi[0];
        float l0 = amp * cosf(ph), l1 = amp * sinf(ph);
        // MLP waveshaper
        float h[16];
#pragma unroll
        for (int q = 0; q < 16; q++)
            h[q] = tanhf(l0 * W_in[q] + l1 * W_in[16 + q] + b_in[q]);
        for (int lay = 0; lay < 2; lay++) {
            float hn[16];
#pragma unroll
            for (int q = 0; q < 16; q++) {
                float s = b_h[lay * 16 + q];
#pragma unroll
                for (int i = 0; i < 16; i++)
                    s += h[i] * W_h[lay * 256 + i * 16 + q];
                hn[q] = tanhf(s);
            }
#pragma unroll
            for (int q = 0; q < 16; q++) h[q] = hn[q];
        }
        float s = b_out[0];
#pragma unroll
        for (int i = 0; i < 16; i++) s += h[i] * W_out[i];
        float ws = tanhf(s);
        float dd = bias[0] + depth[0] * 0.5f * (1.f + ws);
        float td = tanf(dd);
        float p  = tanhf((1.f - td) / (1.f + td));

        float p2 = p * p, p3 = p2 * p, p4 = p2 * p2;
        float bap[5] = { p4, -4.f * p3, 6.f * p2, -4.f * p, 1.f };
        float aap[5] = { 1.f, -4.f * p, 6.f * p2, -4.f * p3, p4 };
        float ag2 = fabsf(g2[0]);
        float den0 = aap[0] - ag2 * bap[0];
        float* row = sc + threadIdx.x * 10;
#pragma unroll
        for (int k = 0; k < 5; k++) {
            float dk = aap[k] - ag2 * bap[k];
            row[k]     = bap[k] / den0;
            row[5 + k] = dk / den0;
        }
        // second output: p (H,) — duplicate identical writes across blocks are benign
        if (N + t < out_size) out[N + t] = p;
        // defensive tail fill (normally out_size == N + H)
        if (t == H - 1 && blockIdx.x == gridDim.x - 1)
            for (int q2 = N + H; q2 < out_size; q2++) out[q2] = p;
    }
    __syncthreads();

    // ---- per-thread chunk ----
    const int c     = blockFirst + threadIdx.x;
    const int start = c * LCH;
    if (start >= N) return;
    int nstart = start - WARM; if (nstart < 0) nstart = 0;

    const float b0  = bq_dc[0], b1c = bq_ff[0], b2c = bq_ff[1];
    const float a1  = 2.f * tanhf(bq_fb[0]);
    const float aa1 = fabsf(a1);
    const float a2  = ((2.f - aa1) * tanhf(bq_fb[1]) + aa1) * 0.5f;
    const float g1v = g1[0];

    int j = nstart - regionStart;                  // xs logical index
    float x1 = xs[(j - 1) + ((j - 1) >> 5)];
    float x2 = xs[(j - 2) + ((j - 2) >> 5)];
    float f1 = 0.f, f2 = 0.f, f3 = 0.f, f4 = 0.f;
    float y1 = 0.f, y2v = 0.f, y3 = 0.f, y4 = 0.f;

    // segment coefficient cache
    float fi0raw = -1e30f, fi0c = 0.f;
    float cb00=0,cb01=0,cb02=0,cb03=0,cb04=0, cbd0=0,cbd1=0,cbd2=0,cbd3=0,cbd4=0;
    float cd01=0,cd02=0,cd03=0,cd04=0, cdd1=0,cdd2=0,cdd3=0,cdd4=0;

    float nf = (float)nstart;

#define RELOAD(POS)                                                            \
    {                                                                          \
        float fi0 = floorf(POS);                                               \
        if (fi0 != fi0raw) {                                                   \
            fi0raw = fi0;                                                      \
            int i0 = (int)fi0;                                                 \
            i0 = i0 < 0 ? 0 : (i0 > Hm2 ? Hm2 : i0);                           \
            fi0c = (float)i0;                                                  \
            const float* rw = sc + (i0 - h0) * 10;                             \
            cb00 = rw[0];  cb01 = rw[1];  cb02 = rw[2];  cb03 = rw[3];  cb04 = rw[4]; \
            cd01 = rw[6];  cd02 = rw[7];  cd03 = rw[8];  cd04 = rw[9];         \
            cbd0 = rw[10] - cb00; cbd1 = rw[11] - cb01; cbd2 = rw[12] - cb02;  \
            cbd3 = rw[13] - cb03; cbd4 = rw[14] - cb04;                        \
            cdd1 = rw[16] - cd01; cdd2 = rw[17] - cd02;                        \
            cdd3 = rw[18] - cd03; cdd4 = rw[19] - cd04;                        \
        }                                                                      \
    }

#define STEP(XV, JOFF, NOFF, XM1, XM2, H1, H2, H3, H4, HN, Y1, Y2, Y3, Y4, YN, DOST, NI) \
    {                                                                          \
        int jj = j + (JOFF);                                                   \
        XV = xs[jj + (jj >> 5)];                                               \
        float v1 = fmaf(b2c, XM2, fmaf(b1c, XM1, b0 * XV));                    \
        HN = fmaf(-a2, H2, fmaf(-a1, H1, v1));                                 \
        float pos = (nf + (float)(NOFF)) * scaleF;                             \
        RELOAD(pos);                                                           \
        float fr = pos - fi0c;                                                 \
        float c0 = fmaf(fr, cbd0, cb00);                                       \
        float c1 = fmaf(fr, cbd1, cb01);                                       \
        float c2 = fmaf(fr, cbd2, cb02);                                       \
        float c3 = fmaf(fr, cbd3, cb03);                                       \
        float c4 = fmaf(fr, cbd4, cb04);                                       \
        float v = fmaf(c0, HN, fmaf(c1, H1, fmaf(c2, H2, fmaf(c3, H3, c4 * H4)))); \
        float d1 = fmaf(fr, cdd1, cd01);                                       \
        float d2 = fmaf(fr, cdd2, cd02);                                       \
        float d3 = fmaf(fr, cdd3, cd03);                                       \
        float d4 = fmaf(fr, cdd4, cd04);                                       \
        YN = fmaf(-d1, Y1, v - fmaf(d2, Y2, fmaf(d3, Y3, d4 * Y4)));           \
        if (DOST) out[(NI)] = fmaf(g1v, HN, YN);                               \
    }

#define GROUP4(DOST, NBASE)                                                    \
    {                                                                          \
        float xa, xb, xc, xd, ha, hb, hc, hd, ya, yb, yc, yd;                  \
        STEP(xa, 0, 0, x1, x2, f1, f2, f3, f4, ha, y1, y2v, y3, y4, ya, DOST, (NBASE) + 0) \
        STEP(xb, 1, 1, xa, x1, ha, f1, f2, f3, hb, ya, y1, y2v, y3, yb, DOST, (NBASE) + 1) \
        STEP(xc, 2, 2, xb, xa, hb, ha, f1, f2, hc, yb, ya, y1, y2v, yc, DOST, (NBASE) + 2) \
        STEP(xd, 3, 3, xc, xb, hc, hb, ha, f1, hd, yc, yb, ya, y1, yd, DOST, (NBASE) + 3) \
        x2 = xc; x1 = xd;                                                      \
        f4 = ha; f3 = hb; f2 = hc; f1 = hd;                                    \
        y4 = ya; y3 = yb; y2v = yc; y1 = yd;                                   \
        nf += 4.f; j += 4;                                                     \
    }

    // warmup (length = start - nstart, multiple of 4; no stores)
    for (int n = nstart; n < start; n += 4) GROUP4(0, 0)

    // payload: LCH samples (multiple of 4)
    int outLim = out_size < N ? out_size : N;
    if (start + LCH <= outLim) {
        for (int n = start; n < start + LCH; n += 4) GROUP4(1, n)
    } else {
        for (int n = start; n < start + LCH; n += 4) {
            float xa, xb, xc, xd, ha, hb, hc, hd, ya, yb, yc, yd;
            STEP(xa, 0, 0, x1, x2, f1, f2, f3, f4, ha, y1, y2v, y3, y4, ya, (n + 0) < outLim, n + 0)
            STEP(xb, 1, 1, xa, x1, ha, f1, f2, f3, hb, ya, y1, y2v, y3, yb, (n + 1) < outLim, n + 1)
            STEP(xc, 2, 2, xb, xa, hb, ha, f1, f2, hc, yb, ya, y1, y2v, yc, (n + 2) < outLim, n + 2)
            STEP(xd, 3, 3, xc, xb, hc, hb, ha, f1, hd, yc, yb, ya, y1, yd, (n + 3) < outLim, n + 3)
            x2 = xc; x1 = xd;
            f4 = ha; f3 = hb; f2 = hc; f1 = hd;
            y4 = ya; y3 = yb; y2v = yc; y1 = yd;
            nf += 4.f; j += 4;
        }
    }
#undef GROUP4
#undef STEP
#undef RELOAD
}

// ---------------- launch ----------------
extern "C" void kernel_launch(void* const* d_in, const int* in_sizes, int n_in,
                              void* d_out, int out_size)
{
    const float* x      = (const float*)d_in[0];
    const float* g1     = (const float*)d_in[1];
    const float* g2     = (const float*)d_in[2];
    const float* depth  = (const float*)d_in[3];
    const float* bias   = (const float*)d_in[4];
    const float* lfo_o  = (const float*)d_in[5];
    const float* lfo_p  = (const float*)d_in[6];
    const float* lfo_r  = (const float*)d_in[7];
    const float* W_in   = (const float*)d_in[8];
    const float* b_in   = (const float*)d_in[9];
    const float* W_h    = (const float*)d_in[10];
    const float* b_h    = (const float*)d_in[11];
    const float* W_out  = (const float*)d_in[12];
    const float* b_out  = (const float*)d_in[13];
    const float* bq_dc  = (const float*)d_in[14];
    const float* bq_ff  = (const float*)d_in[15];
    const float* bq_fb  = (const float*)d_in[16];
    float* out = (float*)d_out;

    int N = in_sizes[0];
    int H = N / 551 + 1;

    int C = (N + LCH - 1) / LCH;
    int blocks = (C + TPB - 1) / TPB;
    phaser_all<<<blocks, TPB>>>(x, g1, g2, depth, bias, lfo_o, lfo_p, lfo_r,
                                W_in, b_in, W_h, b_h, W_out, b_out,
                                bq_dc, bq_ff, bq_fb,
                                out, N, H, out_size);
}

// round 5
// speedup vs baseline: 1.8688x; 1.2775x over previous
#include <cuda_runtime.h>
#include <math.h>

// ---------------- tuning ----------------
#define LCH  32     // samples per chunk (one chunk per thread)
#define WARM 80     // warmup samples (worst perturbed pole ~0.845 -> 1.4e-6)
#define TPB  128    // threads per block -> block covers TPB*LCH samples
#define NCH  12     // max hop-coefficient rows a block can need (<=10 actual)

// Single fused kernel: per-block hop-coefficient MLP (parallelized across the
// block into shared) + chunked biquad + TV-FIR + TV-LPC with zero-state warmup.
__global__ void __launch_bounds__(TPB)
phaser_all(const float* __restrict__ x,
           const float* __restrict__ g1, const float* __restrict__ g2,
           const float* __restrict__ depth, const float* __restrict__ bias,
           const float* __restrict__ lfo_omega, const float* __restrict__ lfo_phi,
           const float* __restrict__ lfo_r_logit,
           const float* __restrict__ W_in, const float* __restrict__ b_in,
           const float* __restrict__ W_h, const float* __restrict__ b_h,
           const float* __restrict__ W_out, const float* __restrict__ b_out,
           const float* __restrict__ bq_dc, const float* __restrict__ bq_ff,
           const float* __restrict__ bq_fb,
           float* __restrict__ out, int N, int H, int out_size)
{
    constexpr int REGN = TPB * LCH + WARM + 2;
    __shared__ float xs[REGN + (REGN >> 5) + 8];   // pad every 32 -> stride 33
    __shared__ float sc[NCH * 10];                 // per hop: cb[0..4], cd[0..4]
    __shared__ float mh[2][NCH * 16];              // MLP hidden ping-pong

    const int blockFirst  = blockIdx.x * TPB;
    const int regionStart = blockFirst * LCH - WARM - 2;
    const float scaleF = (float)((double)(H - 1) / (double)(N - 1));
    const int Hm2 = (H - 2) > 0 ? (H - 2) : 0;

    // ---- stage x into shared (coalesced; zeros outside [0,N)) ----
    for (int j = threadIdx.x; j < REGN; j += TPB) {
        int g = regionStart + j;
        xs[j + (j >> 5)] = (g >= 0 && g < N) ? x[g] : 0.f;
    }

    // ---- hop-row range this block needs ----
    int nmin = regionStart + 2; if (nmin < 0) nmin = 0;
    int nmax = blockFirst * LCH + TPB * LCH; if (nmax > N) nmax = N;   // exclusive
    int i0min = (int)floorf((float)nmin * scaleF);
    if (i0min < 0) i0min = 0; if (i0min > Hm2) i0min = Hm2;
    int i0max = (int)floorf((float)(nmax - 1) * scaleF);
    if (i0max < 0) i0max = 0; if (i0max > Hm2) i0max = Hm2;
    const int h0 = i0min;
    int nh = i0max + 2 - h0; if (nh > NCH) nh = NCH;
    const int nwork = nh * 16;

    // ---- parallel MLP: layer 0 (one (hop,unit) item per thread) ----
    for (int w = threadIdx.x; w < nwork; w += TPB) {
        int hop = w >> 4, u = w & 15;
        float tf  = (float)(h0 + hop);
        float r   = 1.f / (1.f + expf(-lfo_r_logit[0]));
        float amp = expf(tf * logf(r));             // r^t
        float ph  = lfo_omega[0] * tf + lfo_phi[0];
        float l0 = amp * cosf(ph), l1 = amp * sinf(ph);
        mh[0][w] = tanhf(l0 * W_in[u] + l1 * W_in[16 + u] + b_in[u]);
    }
    __syncthreads();
    // ---- hidden layers 1,2 ----
#pragma unroll
    for (int lay = 0; lay < 2; lay++) {
        for (int w = threadIdx.x; w < nwork; w += TPB) {
            int hop = w >> 4, u = w & 15;
            const float* hv = &mh[lay & 1][hop << 4];
            float s = b_h[lay * 16 + u];
#pragma unroll
            for (int i = 0; i < 16; i++)
                s = fmaf(hv[i], W_h[lay * 256 + i * 16 + u], s);
            mh[(lay & 1) ^ 1][w] = tanhf(s);
        }
        __syncthreads();
    }
    // ---- output + allpass coefficient rows (one thread per hop) ----
    if (threadIdx.x < nh) {
        int t = h0 + threadIdx.x;
        const float* hv = &mh[0][threadIdx.x << 4];
        float s = b_out[0];
#pragma unroll
        for (int i = 0; i < 16; i++) s = fmaf(hv[i], W_out[i], s);
        float ws = tanhf(s);
        float dd = bias[0] + depth[0] * 0.5f * (1.f + ws);
        float td = tanf(dd);
        float p  = tanhf((1.f - td) / (1.f + td));

        float p2 = p * p, p3 = p2 * p, p4 = p2 * p2;
        float bap[5] = { p4, -4.f * p3, 6.f * p2, -4.f * p, 1.f };
        float aap[5] = { 1.f, -4.f * p, 6.f * p2, -4.f * p3, p4 };
        float ag2 = fabsf(g2[0]);
        float den0 = aap[0] - ag2 * bap[0];
        float* row = sc + threadIdx.x * 10;
#pragma unroll
        for (int k = 0; k < 5; k++) {
            float dk = aap[k] - ag2 * bap[k];
            row[k]     = bap[k] / den0;
            row[5 + k] = dk / den0;
        }
        // second output: p (H,) — duplicate identical writes across blocks benign
        if (N + t < out_size) out[N + t] = p;
        if (t == H - 1 && blockIdx.x == gridDim.x - 1)
            for (int q2 = N + H; q2 < out_size; q2++) out[q2] = p;
    }
    __syncthreads();

    // ---- per-thread chunk ----
    const int c     = blockFirst + threadIdx.x;
    const int start = c * LCH;
    if (start >= N) return;
    int nstart = start - WARM; if (nstart < 0) nstart = 0;

    const float b0  = bq_dc[0], b1c = bq_ff[0], b2c = bq_ff[1];
    const float a1  = 2.f * tanhf(bq_fb[0]);
    const float aa1 = fabsf(a1);
    const float a2  = ((2.f - aa1) * tanhf(bq_fb[1]) + aa1) * 0.5f;
    const float g1v = g1[0];

    int j = nstart - regionStart;                  // xs logical index
    float x1 = xs[(j - 1) + ((j - 1) >> 5)];
    float x2 = xs[(j - 2) + ((j - 2) >> 5)];
    float f1 = 0.f, f2 = 0.f, f3 = 0.f, f4 = 0.f;
    float y1 = 0.f, y2v = 0.f, y3 = 0.f, y4 = 0.f;

    // segment coefficient cache
    float fi0raw = -1e30f, fi0c = 0.f;
    float cb00=0,cb01=0,cb02=0,cb03=0,cb04=0, cbd0=0,cbd1=0,cbd2=0,cbd3=0,cbd4=0;
    float cd01=0,cd02=0,cd03=0,cd04=0, cdd1=0,cdd2=0,cdd3=0,cdd4=0;

    float nf = (float)nstart;

#define RELOAD(POS)                                                            \
    {                                                                          \
        float fi0 = floorf(POS);                                               \
        if (fi0 != fi0raw) {                                                   \
            fi0raw = fi0;                                                      \
            int i0 = (int)fi0;                                                 \
            i0 = i0 < 0 ? 0 : (i0 > Hm2 ? Hm2 : i0);                           \
            fi0c = (float)i0;                                                  \
            const float* rw = sc + (i0 - h0) * 10;                             \
            cb00 = rw[0];  cb01 = rw[1];  cb02 = rw[2];  cb03 = rw[3];  cb04 = rw[4]; \
            cd01 = rw[6];  cd02 = rw[7];  cd03 = rw[8];  cd04 = rw[9];         \
            cbd0 = rw[10] - cb00; cbd1 = rw[11] - cb01; cbd2 = rw[12] - cb02;  \
            cbd3 = rw[13] - cb03; cbd4 = rw[14] - cb04;                        \
            cdd1 = rw[16] - cd01; cdd2 = rw[17] - cd02;                        \
            cdd3 = rw[18] - cd03; cdd4 = rw[19] - cd04;                        \
        }                                                                      \
    }

#define STEP(XV, JOFF, NOFF, XM1, XM2, H1, H2, H3, H4, HN, Y1, Y2, Y3, Y4, YN, DOST, NI) \
    {                                                                          \
        int jj = j + (JOFF);                                                   \
        XV = xs[jj + (jj >> 5)];                                               \
        float v1 = fmaf(b2c, XM2, fmaf(b1c, XM1, b0 * XV));                    \
        HN = fmaf(-a2, H2, fmaf(-a1, H1, v1));                                 \
        float pos = (nf + (float)(NOFF)) * scaleF;                             \
        RELOAD(pos);                                                           \
        float fr = pos - fi0c;                                                 \
        float c0 = fmaf(fr, cbd0, cb00);                                       \
        float c1 = fmaf(fr, cbd1, cb01);                                       \
        float c2 = fmaf(fr, cbd2, cb02);                                       \
        float c3 = fmaf(fr, cbd3, cb03);                                       \
        float c4 = fmaf(fr, cbd4, cb04);                                       \
        float v = fmaf(c0, HN, fmaf(c1, H1, fmaf(c2, H2, fmaf(c3, H3, c4 * H4)))); \
        float d1 = fmaf(fr, cdd1, cd01);                                       \
        float d2 = fmaf(fr, cdd2, cd02);                                       \
        float d3 = fmaf(fr, cdd3, cd03);                                       \
        float d4 = fmaf(fr, cdd4, cd04);                                       \
        YN = fmaf(-d1, Y1, v - fmaf(d2, Y2, fmaf(d3, Y3, d4 * Y4)));           \
        if (DOST) out[(NI)] = fmaf(g1v, HN, YN);                               \
    }

#define GROUP4(DOST, NBASE)                                                    \
    {                                                                          \
        float xa, xb, xc, xd, ha, hb, hc, hd, ya, yb, yc, yd;                  \
        STEP(xa, 0, 0, x1, x2, f1, f2, f3, f4, ha, y1, y2v, y3, y4, ya, DOST, (NBASE) + 0) \
        STEP(xb, 1, 1, xa, x1, ha, f1, f2, f3, hb, ya, y1, y2v, y3, yb, DOST, (NBASE) + 1) \
        STEP(xc, 2, 2, xb, xa, hb, ha, f1, f2, hc, yb, ya, y1, y2v, yc, DOST, (NBASE) + 2) \
        STEP(xd, 3, 3, xc, xb, hc, hb, ha, f1, hd, yc, yb, ya, y1, yd, DOST, (NBASE) + 3) \
        x2 = xc; x1 = xd;                                                      \
        f4 = ha; f3 = hb; f2 = hc; f1 = hd;                                    \
        y4 = ya; y3 = yb; y2v = yc; y1 = yd;                                   \
        nf += 4.f; j += 4;                                                     \
    }

    // warmup (length = start - nstart, multiple of 4; no stores)
    for (int n = nstart; n < start; n += 4) GROUP4(0, 0)

    // payload: LCH samples (multiple of 4)
    int outLim = out_size < N ? out_size : N;
    if (start + LCH <= outLim) {
        for (int n = start; n < start + LCH; n += 4) GROUP4(1, n)
    } else {
        for (int n = start; n < start + LCH; n += 4) {
            float xa, xb, xc, xd, ha, hb, hc, hd, ya, yb, yc, yd;
            STEP(xa, 0, 0, x1, x2, f1, f2, f3, f4, ha, y1, y2v, y3, y4, ya, (n + 0) < outLim, n + 0)
            STEP(xb, 1, 1, xa, x1, ha, f1, f2, f3, hb, ya, y1, y2v, y3, yb, (n + 1) < outLim, n + 1)
            STEP(xc, 2, 2, xb, xa, hb, ha, f1, f2, hc, yb, ya, y1, y2v, yc, (n + 2) < outLim, n + 2)
            STEP(xd, 3, 3, xc, xb, hc, hb, ha, f1, hd, yc, yb, ya, y1, yd, (n + 3) < outLim, n + 3)
            x2 = xc; x1 = xd;
            f4 = ha; f3 = hb; f2 = hc; f1 = hd;
            y4 = ya; y3 = yb; y2v = yc; y1 = yd;
            nf += 4.f; j += 4;
        }
    }
#undef GROUP4
#undef STEP
#undef RELOAD
}

// ---------------- launch ----------------
extern "C" void kernel_launch(void* const* d_in, const int* in_sizes, int n_in,
                              void* d_out, int out_size)
{
    const float* x      = (const float*)d_in[0];
    const float* g1     = (const float*)d_in[1];
    const float* g2     = (const float*)d_in[2];
    const float* depth  = (const float*)d_in[3];
    const float* bias   = (const float*)d_in[4];
    const float* lfo_o  = (const float*)d_in[5];
    const float* lfo_p  = (const float*)d_in[6];
    const float* lfo_r  = (const float*)d_in[7];
    const float* W_in   = (const float*)d_in[8];
    const float* b_in   = (const float*)d_in[9];
    const float* W_h    = (const float*)d_in[10];
    const float* b_h    = (const float*)d_in[11];
    const float* W_out  = (const float*)d_in[12];
    const float* b_out  = (const float*)d_in[13];
    const float* bq_dc  = (const float*)d_in[14];
    const float* bq_ff  = (const float*)d_in[15];
    const float* bq_fb  = (const float*)d_in[16];
    float* out = (float*)d_out;

    int N = in_sizes[0];
    int H = N / 551 + 1;

    int C = (N + LCH - 1) / LCH;
    int blocks = (C + TPB - 1) / TPB;
    phaser_all<<<blocks, TPB>>>(x, g1, g2, depth, bias, lfo_o, lfo_p, lfo_r,
                                W_in, b_in, W_h, b_h, W_out, b_out,
                                bq_dc, bq_ff, bq_fb,
                                out, N, H, out_size);
}

// round 8
// speedup vs baseline: 1.8716x; 1.0015x over previous
#include <cuda_runtime.h>
#include <math.h>

// ---------------- tuning ----------------
#define LCH  32     // samples per chunk (one chunk per thread)
#define WARM 80     // warmup samples (worst perturbed pole ~0.845 -> 1.4e-6)
#define TPB  32     // one warp per block -> 1024 blocks, near-perfect balance
#define NCH  6      // max hop rows per block region (1106 samples -> <=5)

__global__ void __launch_bounds__(TPB)
phaser_all(const float* __restrict__ x,
           const float* __restrict__ g1, const float* __restrict__ g2,
           const float* __restrict__ depth, const float* __restrict__ bias,
           const float* __restrict__ lfo_omega, const float* __restrict__ lfo_phi,
           const float* __restrict__ lfo_r_logit,
           const float* __restrict__ W_in, const float* __restrict__ b_in,
           const float* __restrict__ W_h, const float* __restrict__ b_h,
           const float* __restrict__ W_out, const float* __restrict__ b_out,
           const float* __restrict__ bq_dc, const float* __restrict__ bq_ff,
           const float* __restrict__ bq_fb,
           float* __restrict__ out, int N, int H, int out_size)
{
    constexpr int REGN = TPB * LCH + WARM + 2;     // 1106
    __shared__ float xs[REGN + (REGN >> 5) + 8];   // pad every 32 -> stride 33
    __shared__ float sc[NCH * 10];                 // per hop: cb[0..4], cd[0..4]
    __shared__ float mh[2][NCH * 16];              // MLP hidden ping-pong

    const int blockFirst  = blockIdx.x * TPB;
    const int regionStart = blockFirst * LCH - WARM - 2;
    const float scaleF = (float)((double)(H - 1) / (double)(N - 1));
    const int Hm2 = (H - 2) > 0 ? (H - 2) : 0;

    // ---- stage x into shared (coalesced; zeros outside [0,N)) ----
    for (int j = threadIdx.x; j < REGN; j += TPB) {
        int g = regionStart + j;
        xs[j + (j >> 5)] = (g >= 0 && g < N) ? x[g] : 0.f;
    }

    // ---- hop-row range this block needs ----
    int nmin = regionStart + 2; if (nmin < 0) nmin = 0;
    int nmaxx = blockFirst * LCH + TPB * LCH; if (nmaxx > N) nmaxx = N;
    int i0min = (int)floorf((float)nmin * scaleF);
    if (i0min < 0) i0min = 0; if (i0min > Hm2) i0min = Hm2;
    int i0max = (int)floorf((float)(nmaxx - 1) * scaleF);
    if (i0max < 0) i0max = 0; if (i0max > Hm2) i0max = Hm2;
    const int h0 = i0min;
    int nh = i0max + 2 - h0; if (nh > NCH) nh = NCH;
    const int nwork = nh * 16;

    // ---- parallel MLP: layer 0 ----
    for (int w = threadIdx.x; w < nwork; w += TPB) {
        int hop = w >> 4, u = w & 15;
        float tf  = (float)(h0 + hop);
        float r   = 1.f / (1.f + expf(-lfo_r_logit[0]));
        float amp = expf(tf * logf(r));             // r^t
        float ph  = lfo_omega[0] * tf + lfo_phi[0];
        float l0 = amp * cosf(ph), l1 = amp * sinf(ph);
        mh[0][w] = tanhf(l0 * W_in[u] + l1 * W_in[16 + u] + b_in[u]);
    }
    __syncthreads();
#pragma unroll
    for (int lay = 0; lay < 2; lay++) {
        for (int w = threadIdx.x; w < nwork; w += TPB) {
            int hop = w >> 4, u = w & 15;
            const float* hv = &mh[lay & 1][hop << 4];
            float s = b_h[lay * 16 + u];
#pragma unroll
            for (int i = 0; i < 16; i++)
                s = fmaf(hv[i], W_h[lay * 256 + i * 16 + u], s);
            mh[(lay & 1) ^ 1][w] = tanhf(s);
        }
        __syncthreads();
    }
    // ---- output layer + allpass coefficient rows (one thread per hop) ----
    if (threadIdx.x < nh) {
        int t = h0 + threadIdx.x;
        const float* hv = &mh[0][threadIdx.x << 4];
        float s = b_out[0];
#pragma unroll
        for (int i = 0; i < 16; i++) s = fmaf(hv[i], W_out[i], s);
        float ws = tanhf(s);
        float dd = bias[0] + depth[0] * 0.5f * (1.f + ws);
        float td = tanf(dd);
        float p  = tanhf((1.f - td) / (1.f + td));
        float p2 = p * p, p3 = p2 * p, p4 = p2 * p2;
        float bap[5] = { p4, -4.f * p3, 6.f * p2, -4.f * p, 1.f };
        float aap[5] = { 1.f, -4.f * p, 6.f * p2, -4.f * p3, p4 };
        float ag2 = fabsf(g2[0]);
        float den0 = aap[0] - ag2 * bap[0];
        float* row = sc + threadIdx.x * 10;
#pragma unroll
        for (int k = 0; k < 5; k++) {
            float dk = aap[k] - ag2 * bap[k];
            row[k]     = bap[k] / den0;
            row[5 + k] = dk / den0;
        }
        if (N + t < out_size) out[N + t] = p;       // second output: p (H,)
        if (t == H - 1 && blockIdx.x == gridDim.x - 1)
            for (int q2 = N + H; q2 < out_size; q2++) out[q2] = p;
    }
    __syncthreads();

    // ---- per-thread chunk ----
    const int c     = blockFirst + threadIdx.x;
    const int start = c * LCH;
    if (start >= N) return;
    int nstart = start - WARM; if (nstart < 0) nstart = 0;
    int nend   = start + LCH;  if (nend > N)   nend = N;

    const float b0  = bq_dc[0], b1c = bq_ff[0], b2c = bq_ff[1];
    const float a1  = 2.f * tanhf(bq_fb[0]);
    const float aa1 = fabsf(a1);
    const float a2  = ((2.f - aa1) * tanhf(bq_fb[1]) + aa1) * 0.5f;
    const float g1v = g1[0];
    const int outLim = out_size < N ? out_size : N;

    int j = nstart - regionStart;                  // xs logical index
    float x1 = xs[(j - 1) + ((j - 1) >> 5)];
    float x2 = xs[(j - 2) + ((j - 2) >> 5)];
    float f1 = 0.f, f2 = 0.f, f3 = 0.f, f4 = 0.f;
    float y1 = 0.f, y2v = 0.f, y3 = 0.f, y4 = 0.f;

    // coefficient registers + running frac
    float cb00,cb01,cb02,cb03,cb04, cbd0,cbd1,cbd2,cbd3,cbd4;
    float cd01,cd02,cd03,cd04, cdd1,cdd2,cdd3,cdd4;
    int i0;
    const float* rw;
    float fr, frLim;

#define RELOAD_ROWS()                                                          \
    {                                                                          \
        cb00 = rw[0];  cb01 = rw[1];  cb02 = rw[2];  cb03 = rw[3];  cb04 = rw[4]; \
        cd01 = rw[6];  cd02 = rw[7];  cd03 = rw[8];  cd04 = rw[9];             \
        cbd0 = rw[10] - cb00; cbd1 = rw[11] - cb01; cbd2 = rw[12] - cb02;      \
        cbd3 = rw[13] - cb03; cbd4 = rw[14] - cb04;                            \
        cdd1 = rw[16] - cd01; cdd2 = rw[17] - cd02;                            \
        cdd3 = rw[18] - cd03; cdd4 = rw[19] - cd04;                            \
        frLim = (i0 < Hm2) ? 1.0f : 1e30f;                                     \
    }

    {
        float pos0 = (float)nstart * scaleF;       // exact reference seed
        i0 = (int)floorf(pos0);
        i0 = i0 < 0 ? 0 : (i0 > Hm2 ? Hm2 : i0);
        rw = sc + (i0 - h0) * 10;
        RELOAD_ROWS();
        fr = pos0 - (float)i0;
    }

    // one step: crossing check (rare) + biquad + TV-FIR + TV-LPC
#define STEP(XV, XM1, XM2, H1, H2, H3, H4, HN, Y1, Y2, Y3, Y4, YN, K, DOST)    \
    {                                                                          \
        if (fr >= frLim) {                                                     \
            i0++; rw += 10;                                                    \
            RELOAD_ROWS();                                                     \
            fr -= 1.0f;                                                        \
        }                                                                      \
        int jj = j + (K);                                                      \
        XV = xs[jj + (jj >> 5)];                                               \
        float v1 = fmaf(b2c, XM2, fmaf(b1c, XM1, b0 * XV));                    \
        HN = fmaf(-a2, H2, fmaf(-a1, H1, v1));                                 \
        float c0 = fmaf(fr, cbd0, cb00);                                       \
        float c1 = fmaf(fr, cbd1, cb01);                                       \
        float c2 = fmaf(fr, cbd2, cb02);                                       \
        float c3 = fmaf(fr, cbd3, cb03);                                       \
        float c4 = fmaf(fr, cbd4, cb04);                                       \
        float v = fmaf(c0, HN, fmaf(c1, H1, fmaf(c2, H2, fmaf(c3, H3, c4 * H4)))); \
        float d1 = fmaf(fr, cdd1, cd01);                                       \
        float d2 = fmaf(fr, cdd2, cd02);                                       \
        float d3 = fmaf(fr, cdd3, cd03);                                       \
        float d4 = fmaf(fr, cdd4, cd04);                                       \
        YN = fmaf(-d1, Y1, v - fmaf(d2, Y2, fmaf(d3, Y3, d4 * Y4)));           \
        fr += scaleF;                                                          \
        if (DOST) out[n + (K)] = fmaf(g1v, HN, YN);                            \
    }

#define GROUP4(DOST)                                                           \
    {                                                                          \
        float xa, xb, xc, xd, ha, hb, hc, hd, ya, yb, yc, yd;                  \
        STEP(xa, x1, x2, f1, f2, f3, f4, ha, y1, y2v, y3, y4, ya, 0, DOST)     \
        STEP(xb, xa, x1, ha, f1, f2, f3, hb, ya, y1, y2v, y3, yb, 1, DOST)     \
        STEP(xc, xb, xa, hb, ha, f1, f2, hc, yb, ya, y1, y2v, yc, 2, DOST)     \
        STEP(xd, xc, xb, hc, hb, ha, f1, hd, yc, yb, ya, y1, yd, 3, DOST)      \
        x2 = xc; x1 = xd;                                                      \
        f4 = ha; f3 = hb; f2 = hc; f1 = hd;                                    \
        y4 = ya; y3 = yb; y2v = yc; y1 = yd;                                   \
        j += 4;                                                                \
    }

    int n = nstart;
    if (((nend - nstart) & 3) == 0 && nend <= outLim) {
        // fast path: all lengths multiple of 4, stores unguarded
        for (; n < start; n += 4) GROUP4(0)       // warmup
        for (; n < nend;  n += 4) GROUP4(1)       // payload
    } else {
        // generic fallback (guarded stores / odd lengths)
        for (; n < nend; ++n) {
            if (fr >= frLim) {
                i0++; rw += 10;
                RELOAD_ROWS();
                fr -= 1.0f;
            }
            float xv = xs[j + (j >> 5)];
            float v1 = fmaf(b2c, x2, fmaf(b1c, x1, b0 * xv));
            x2 = x1; x1 = xv;
            float hcur = fmaf(-a2, f2, fmaf(-a1, f1, v1));
            float c0 = fmaf(fr, cbd0, cb00);
            float c1 = fmaf(fr, cbd1, cb01);
            float c2 = fmaf(fr, cbd2, cb02);
            float c3 = fmaf(fr, cbd3, cb03);
            float c4 = fmaf(fr, cbd4, cb04);
            float v = fmaf(c0, hcur, fmaf(c1, f1, fmaf(c2, f2, fmaf(c3, f3, c4 * f4))));
            float d1 = fmaf(fr, cdd1, cd01);
            float d2 = fmaf(fr, cdd2, cd02);
            float d3 = fmaf(fr, cdd3, cd03);
            float d4 = fmaf(fr, cdd4, cd04);
            float yv = fmaf(-d1, y1, v - fmaf(d2, y2v, fmaf(d3, y3, d4 * y4)));
            y4 = y3; y3 = y2v; y2v = y1; y1 = yv;
            f4 = f3; f3 = f2; f2 = f1; f1 = hcur;
            fr += scaleF;
            j++;
            if (n >= start && n < outLim) out[n] = fmaf(g1v, hcur, yv);
        }
    }
#undef GROUP4
#undef STEP
#undef RELOAD_ROWS
}

// ---------------- launch ----------------
extern "C" void kernel_launch(void* const* d_in, const int* in_sizes, int n_in,
                              void* d_out, int out_size)
{
    const float* x      = (const float*)d_in[0];
    const float* g1     = (const float*)d_in[1];
    const float* g2     = (const float*)d_in[2];
    const float* depth  = (const float*)d_in[3];
    const float* bias   = (const float*)d_in[4];
    const float* lfo_o  = (const float*)d_in[5];
    const float* lfo_p  = (const float*)d_in[6];
    const float* lfo_r  = (const float*)d_in[7];
    const float* W_in   = (const float*)d_in[8];
    const float* b_in   = (const float*)d_in[9];
    const float* W_h    = (const float*)d_in[10];
    const float* b_h    = (const float*)d_in[11];
    const float* W_out  = (const float*)d_in[12];
    const float* b_out  = (const float*)d_in[13];
    const float* bq_dc  = (const float*)d_in[14];
    const float* bq_ff  = (const float*)d_in[15];
    const float* bq_fb  = (const float*)d_in[16];
    float* out = (float*)d_out;

    int N = in_sizes[0];
    int H = N / 551 + 1;

    int C = (N + LCH - 1) / LCH;
    int blocks = (C + TPB - 1) / TPB;
    phaser_all<<<blocks, TPB>>>(x, g1, g2, depth, bias, lfo_o, lfo_p, lfo_r,
                                W_in, b_in, W_h, b_h, W_out, b_out,
                                bq_dc, bq_ff, bq_fb,
                                out, N, H, out_size);
}

// round 9
// speedup vs baseline: 2.3510x; 1.2562x over previous
#include <cuda_runtime.h>
#include <math.h>

// ---------------- tuning ----------------
#define LCH  32     // samples per chunk (one chunk per thread)
#define WARM 64     // warmup (dominant perturbed pole ~0.844 -> 0.844^64 ~ 2e-5)
#define TPB  32     // one warp per block -> 1024 blocks, near-perfect balance
#define NCH  6      // max hop rows per block region (1090 samples -> <=4)

__global__ void __launch_bounds__(TPB)
phaser_all(const float* __restrict__ x,
           const float* __restrict__ g1, const float* __restrict__ g2,
           const float* __restrict__ depth, const float* __restrict__ bias,
           const float* __restrict__ lfo_omega, const float* __restrict__ lfo_phi,
           const float* __restrict__ lfo_r_logit,
           const float* __restrict__ W_in, const float* __restrict__ b_in,
           const float* __restrict__ W_h, const float* __restrict__ b_h,
           const float* __restrict__ W_out, const float* __restrict__ b_out,
           const float* __restrict__ bq_dc, const float* __restrict__ bq_ff,
           const float* __restrict__ bq_fb,
           float* __restrict__ out, int N, int H, int out_size)
{
    constexpr int REGN = TPB * LCH + WARM + 2;     // 1090
    constexpr int PAYN = TPB * LCH;                // 1024
    __shared__ float xs[REGN + (REGN >> 5) + 8];   // pad every 32 -> stride 33
    __shared__ float ys[PAYN + (PAYN >> 5) + 8];   // staged output (padded)
    __shared__ float sc[NCH * 10];                 // per hop: cb[0..4], cd[0..4]
    __shared__ float mh[2][NCH * 16];              // MLP hidden ping-pong

    const int blockFirst  = blockIdx.x * TPB;
    const int blockSampleBase = blockFirst * LCH;
    const int regionStart = blockSampleBase - WARM - 2;
    const float scaleF = (float)((double)(H - 1) / (double)(N - 1));
    const int Hm2 = (H - 2) > 0 ? (H - 2) : 0;

    // ---- stage x into shared (coalesced; zeros outside [0,N)) ----
    for (int j = threadIdx.x; j < REGN; j += TPB) {
        int g = regionStart + j;
        xs[j + (j >> 5)] = (g >= 0 && g < N) ? x[g] : 0.f;
    }

    // ---- hop-row range this block needs ----
    int nmin = regionStart + 2; if (nmin < 0) nmin = 0;
    int nmaxx = blockSampleBase + PAYN; if (nmaxx > N) nmaxx = N;
    int i0min = (int)floorf((float)nmin * scaleF);
    if (i0min < 0) i0min = 0; if (i0min > Hm2) i0min = Hm2;
    int i0max = (int)floorf((float)(nmaxx - 1) * scaleF);
    if (i0max < 0) i0max = 0; if (i0max > Hm2) i0max = Hm2;
    const int h0 = i0min;
    int nh = i0max + 2 - h0; if (nh > NCH) nh = NCH;
    const int nwork = nh * 16;

    // ---- parallel MLP: layer 0 ----
    {
        float r    = 1.f / (1.f + expf(-lfo_r_logit[0]));
        float logr = logf(r);
        float om = lfo_omega[0], phi = lfo_phi[0];
        for (int w = threadIdx.x; w < nwork; w += TPB) {
            int hop = w >> 4, u = w & 15;
            float tf  = (float)(h0 + hop);
            float amp = expf(tf * logr);            // r^t
            float ph  = om * tf + phi;
            float l0 = amp * cosf(ph), l1 = amp * sinf(ph);
            mh[0][w] = tanhf(l0 * W_in[u] + l1 * W_in[16 + u] + b_in[u]);
        }
    }
    __syncthreads();
#pragma unroll
    for (int lay = 0; lay < 2; lay++) {
        for (int w = threadIdx.x; w < nwork; w += TPB) {
            int hop = w >> 4, u = w & 15;
            const float* hv = &mh[lay & 1][hop << 4];
            float s = b_h[lay * 16 + u];
#pragma unroll
            for (int i = 0; i < 16; i++)
                s = fmaf(hv[i], W_h[lay * 256 + i * 16 + u], s);
            mh[(lay & 1) ^ 1][w] = tanhf(s);
        }
        __syncthreads();
    }
    // ---- output layer + allpass coefficient rows (one thread per hop) ----
    if (threadIdx.x < nh) {
        int t = h0 + threadIdx.x;
        const float* hv = &mh[0][threadIdx.x << 4];
        float s = b_out[0];
#pragma unroll
        for (int i = 0; i < 16; i++) s = fmaf(hv[i], W_out[i], s);
        float ws = tanhf(s);
        float dd = bias[0] + depth[0] * 0.5f * (1.f + ws);
        float td = tanf(dd);
        float p  = tanhf((1.f - td) / (1.f + td));
        float p2 = p * p, p3 = p2 * p, p4 = p2 * p2;
        float bap[5] = { p4, -4.f * p3, 6.f * p2, -4.f * p, 1.f };
        float aap[5] = { 1.f, -4.f * p, 6.f * p2, -4.f * p3, p4 };
        float ag2 = fabsf(g2[0]);
        float den0 = aap[0] - ag2 * bap[0];
        float* row = sc + threadIdx.x * 10;
#pragma unroll
        for (int k = 0; k < 5; k++) {
            float dk = aap[k] - ag2 * bap[k];
            row[k]     = bap[k] / den0;
            row[5 + k] = dk / den0;
        }
        if (N + t < out_size) out[N + t] = p;       // second output: p (H,)
        if (t == H - 1 && blockIdx.x == gridDim.x - 1)
            for (int q2 = N + H; q2 < out_size; q2++) out[q2] = p;
    }
    __syncthreads();

    // ---- per-thread chunk ----
    const int c     = blockFirst + threadIdx.x;
    const int start = c * LCH;
    if (start < N) {
        int nstart = start - WARM; if (nstart < 0) nstart = 0;
        int nend   = start + LCH;  if (nend > N)   nend = N;

        const float b0  = bq_dc[0], b1c = bq_ff[0], b2c = bq_ff[1];
        const float a1  = 2.f * tanhf(bq_fb[0]);
        const float aa1 = fabsf(a1);
        const float a2  = ((2.f - aa1) * tanhf(bq_fb[1]) + aa1) * 0.5f;
        const float g1v = g1[0];

        int j = nstart - regionStart;              // xs logical index
        float x1 = xs[(j - 1) + ((j - 1) >> 5)];
        float x2 = xs[(j - 2) + ((j - 2) >> 5)];
        float f1 = 0.f, f2 = 0.f, f3 = 0.f, f4 = 0.f;
        float y1 = 0.f, y2v = 0.f, y3 = 0.f, y4 = 0.f;

        float cb00,cb01,cb02,cb03,cb04, cbd0,cbd1,cbd2,cbd3,cbd4;
        float cd01,cd02,cd03,cd04, cdd1,cdd2,cdd3,cdd4;
        int i0;
        const float* rw;
        float fr, frLim;

#define RELOAD_ROWS()                                                          \
    {                                                                          \
        cb00 = rw[0];  cb01 = rw[1];  cb02 = rw[2];  cb03 = rw[3];  cb04 = rw[4]; \
        cd01 = rw[6];  cd02 = rw[7];  cd03 = rw[8];  cd04 = rw[9];             \
        cbd0 = rw[10] - cb00; cbd1 = rw[11] - cb01; cbd2 = rw[12] - cb02;      \
        cbd3 = rw[13] - cb03; cbd4 = rw[14] - cb04;                            \
        cdd1 = rw[16] - cd01; cdd2 = rw[17] - cd02;                            \
        cdd3 = rw[18] - cd03; cdd4 = rw[19] - cd04;                            \
        frLim = (i0 < Hm2) ? 1.0f : 1e30f;                                     \
    }

        {
            float pos0 = (float)nstart * scaleF;   // exact reference seed
            i0 = (int)floorf(pos0);
            i0 = i0 < 0 ? 0 : (i0 > Hm2 ? Hm2 : i0);
            rw = sc + (i0 - h0) * 10;
            RELOAD_ROWS();
            fr = pos0 - (float)i0;
        }

        // one step; DOST: 0 = no store, 1 = store to ys at (Q)+(K)
#define STEP(XV, XM1, XM2, H1, H2, H3, H4, HN, Y1, Y2, Y3, Y4, YN, K, DOST, Q) \
    {                                                                          \
        if (fr >= frLim) {                                                     \
            i0++; rw += 10;                                                    \
            RELOAD_ROWS();                                                     \
            fr -= 1.0f;                                                        \
        }                                                                      \
        int jj = j + (K);                                                      \
        XV = xs[jj + (jj >> 5)];                                               \
        float v1 = fmaf(b2c, XM2, fmaf(b1c, XM1, b0 * XV));                    \
        HN = fmaf(-a2, H2, fmaf(-a1, H1, v1));                                 \
        float c0 = fmaf(fr, cbd0, cb00);                                       \
        float c1 = fmaf(fr, cbd1, cb01);                                       \
        float c2 = fmaf(fr, cbd2, cb02);                                       \
        float c3 = fmaf(fr, cbd3, cb03);                                       \
        float c4 = fmaf(fr, cbd4, cb04);                                       \
        float v = fmaf(c0, HN, fmaf(c1, H1, fmaf(c2, H2, fmaf(c3, H3, c4 * H4)))); \
        float d1 = fmaf(fr, cdd1, cd01);                                       \
        float d2 = fmaf(fr, cdd2, cd02);                                       \
        float d3 = fmaf(fr, cdd3, cd03);                                       \
        float d4 = fmaf(fr, cdd4, cd04);                                       \
        YN = fmaf(-d1, Y1, v - fmaf(d2, Y2, fmaf(d3, Y3, d4 * Y4)));           \
        fr += scaleF;                                                          \
        if (DOST) {                                                            \
            int qq = (Q) + (K);                                                \
            ys[qq + (qq >> 5)] = fmaf(g1v, HN, YN);                            \
        }                                                                      \
    }

#define GROUP4(DOST, Q)                                                        \
    {                                                                          \
        float xa, xb, xc, xd, ha, hb, hc, hd, ya, yb, yc, yd;                  \
        STEP(xa, x1, x2, f1, f2, f3, f4, ha, y1, y2v, y3, y4, ya, 0, DOST, Q)  \
        STEP(xb, xa, x1, ha, f1, f2, f3, hb, ya, y1, y2v, y3, yb, 1, DOST, Q)  \
        STEP(xc, xb, xa, hb, ha, f1, f2, hc, yb, ya, y1, y2v, yc, 2, DOST, Q)  \
        STEP(xd, xc, xb, hc, hb, ha, f1, hd, yc, yb, ya, y1, yd, 3, DOST, Q)   \
        x2 = xc; x1 = xd;                                                      \
        f4 = ha; f3 = hb; f2 = hc; f1 = hd;                                    \
        y4 = ya; y3 = yb; y2v = yc; y1 = yd;                                   \
        j += 4;                                                                \
    }

        int n = nstart;
        if (((nend - nstart) & 3) == 0) {
            // fast path: warmup then payload (stores into shared ys)
            for (; n < start; n += 4) GROUP4(0, 0)
            int q = threadIdx.x * LCH;
            for (; n < nend; n += 4) { GROUP4(1, q) q += 4; }
        } else {
            // generic fallback (odd lengths; writes ys for payload samples)
            int q = threadIdx.x * LCH;
            for (; n < nend; ++n) {
                if (fr >= frLim) {
                    i0++; rw += 10;
                    RELOAD_ROWS();
                    fr -= 1.0f;
                }
                float xv = xs[j + (j >> 5)];
                float v1 = fmaf(b2c, x2, fmaf(b1c, x1, b0 * xv));
                x2 = x1; x1 = xv;
                float hcur = fmaf(-a2, f2, fmaf(-a1, f1, v1));
                float c0 = fmaf(fr, cbd0, cb00);
                float c1 = fmaf(fr, cbd1, cb01);
                float c2 = fmaf(fr, cbd2, cb02);
                float c3 = fmaf(fr, cbd3, cb03);
                float c4 = fmaf(fr, cbd4, cb04);
                float v = fmaf(c0, hcur, fmaf(c1, f1, fmaf(c2, f2, fmaf(c3, f3, c4 * f4))));
                float d1 = fmaf(fr, cdd1, cd01);
                float d2 = fmaf(fr, cdd2, cd02);
                float d3 = fmaf(fr, cdd3, cd03);
                float d4 = fmaf(fr, cdd4, cd04);
                float yv = fmaf(-d1, y1, v - fmaf(d2, y2v, fmaf(d3, y3, d4 * y4)));
                y4 = y3; y3 = y2v; y2v = y1; y1 = yv;
                f4 = f3; f3 = f2; f2 = f1; f1 = hcur;
                fr += scaleF;
                j++;
                if (n >= start) { ys[q + (q >> 5)] = fmaf(g1v, hcur, yv); q++; }
            }
        }
#undef GROUP4
#undef STEP
#undef RELOAD_ROWS
    }
    __syncthreads();

    // ---- coalesced epilogue: shared ys -> global out ----
    {
        const int outLim = out_size < N ? out_size : N;
        for (int idx = threadIdx.x; idx < PAYN; idx += TPB) {
            int g = blockSampleBase + idx;
            if (g < outLim) out[g] = ys[idx + (idx >> 5)];
        }
    }
}

// ---------------- launch ----------------
extern "C" void kernel_launch(void* const* d_in, const int* in_sizes, int n_in,
                              void* d_out, int out_size)
{
    const float* x      = (const float*)d_in[0];
    const float* g1     = (const float*)d_in[1];
    const float* g2     = (const float*)d_in[2];
    const float* depth  = (const float*)d_in[3];
    const float* bias   = (const float*)d_in[4];
    const float* lfo_o  = (const float*)d_in[5];
    const float* lfo_p  = (const float*)d_in[6];
    const float* lfo_r  = (const float*)d_in[7];
    const float* W_in   = (const float*)d_in[8];
    const float* b_in   = (const float*)d_in[9];
    const float* W_h    = (const float*)d_in[10];
    const float* b_h    = (const float*)d_in[11];
    const float* W_out  = (const float*)d_in[12];
    const float* b_out  = (const float*)d_in[13];
    const float* bq_dc  = (const float*)d_in[14];
    const float* bq_ff  = (const float*)d_in[15];
    const float* bq_fb  = (const float*)d_in[16];
    float* out = (float*)d_out;

    int N = in_sizes[0];
    int H = N / 551 + 1;

    int C = (N + LCH - 1) / LCH;
    int blocks = (C + TPB - 1) / TPB;
    phaser_all<<<blocks, TPB>>>(x, g1, g2, depth, bias, lfo_o, lfo_p, lfo_r,
                                W_in, b_in, W_h, b_h, W_out, b_out,
                                bq_dc, bq_ff, bq_fb,
                                out, N, H, out_size);
}